// round 2
// baseline (speedup 1.0000x reference)
#include <cuda_runtime.h>
#include <cuda_bf16.h>
#include <math.h>

// Problem dims
#define Bn 16384
#define Nn 64
#define Fn 128
#define Kn 64

// Scratch (device globals; no allocation allowed)
__device__ float gW[Nn * Fn * Kn];   // W[n] = D[n] * L^{-T}  (2 MB)
__device__ float gQ[Nn * Bn];        // q[n,b] = ||W[n]^T x_b||^2 (4 MB)

// ---- packed f32x2 helpers (doubles fp32 FMA throughput on sm_103a) ----
__device__ __forceinline__ unsigned long long pack2(float a, float b) {
    unsigned long long r;
    asm("mov.b64 %0, {%1, %2};" : "=l"(r) : "f"(a), "f"(b));
    return r;
}
__device__ __forceinline__ void fma2(unsigned long long &d, unsigned long long a, unsigned long long b) {
    asm("fma.rn.f32x2 %0, %1, %2, %0;" : "+l"(d) : "l"(a), "l"(b));
}
__device__ __forceinline__ void unpack2(unsigned long long v, float &a, float &b) {
    asm("mov.b64 {%0, %1}, %2;" : "=f"(a), "=f"(b) : "l"(v));
}

// ============================================================================
// Kernel 1: per cluster n: A = D^T D ; Cholesky A = L L^T ; Linv = L^{-1} ;
//           W = D * Linv^T   (so W^T x = L^{-1} D^T x, and ||W^T x||^2 = q)
// 64 blocks x 256 threads. Dynamic smem: sD(8192) + sA(64*65) + sL(64*65) floats.
// ============================================================================
__global__ void __launch_bounds__(256) prep_kernel(const float* __restrict__ D) {
    extern __shared__ float sm[];
    float* sD = sm;                     // [128][64]
    float* sA = sm + Fn * Kn;           // [64][65] padded
    float* sL = sA + 64 * 65;           // [64][65] padded

    const int n = blockIdx.x, tid = threadIdx.x;
    const float* Dn = D + n * Fn * Kn;

    for (int idx = tid; idx < Fn * Kn; idx += 256) sD[idx] = Dn[idx];
    __syncthreads();

    // --- DTD: A[j][k] = sum_i D[i][j] D[i][k] ; 4x4 microtile per thread ---
    {
        const int tj = tid >> 4, tk = tid & 15;
        const int j0 = tj * 4, k0 = tk * 4;
        float acc[4][4];
        #pragma unroll
        for (int a = 0; a < 4; a++)
            #pragma unroll
            for (int b = 0; b < 4; b++) acc[a][b] = 0.f;
        for (int i = 0; i < Fn; i++) {
            float av[4], bv[4];
            #pragma unroll
            for (int a = 0; a < 4; a++) av[a] = sD[i * 64 + j0 + a];
            #pragma unroll
            for (int b = 0; b < 4; b++) bv[b] = sD[i * 64 + k0 + b];
            #pragma unroll
            for (int a = 0; a < 4; a++)
                #pragma unroll
                for (int b = 0; b < 4; b++) acc[a][b] += av[a] * bv[b];
        }
        #pragma unroll
        for (int a = 0; a < 4; a++)
            #pragma unroll
            for (int b = 0; b < 4; b++) sA[(j0 + a) * 65 + (k0 + b)] = acc[a][b];
    }
    __syncthreads();

    // --- Cholesky (lower), in place in sA ---
    for (int k = 0; k < 64; k++) {
        if (tid == 0) sA[k * 65 + k] = sqrtf(sA[k * 65 + k]);
        __syncthreads();
        if (tid > k && tid < 64) sA[tid * 65 + k] /= sA[k * 65 + k];
        __syncthreads();
        for (int idx = tid; idx < 64 * 64; idx += 256) {
            int i = idx >> 6, j = idx & 63;
            if (i > k && j > k && j <= i)
                sA[i * 65 + j] -= sA[i * 65 + k] * sA[j * 65 + k];
        }
        __syncthreads();
    }

    // --- Linv = L^{-1} (forward substitution per column, columns in parallel) ---
    for (int j = 0; j < 64; j++) {
        if (tid < 64) {
            int c = tid;
            if (c <= j) {
                float s = (c == j) ? 1.0f : 0.0f;
                for (int m = c; m < j; m++) s -= sA[j * 65 + m] * sL[m * 65 + c];
                sL[j * 65 + c] = s / sA[j * 65 + j];
            } else {
                sL[j * 65 + c] = 0.0f;
            }
        }
        __syncthreads();
    }

    // --- W[i][k] = sum_{j<=k} D[i][j] * Linv[k][j] ---
    for (int idx = tid; idx < Fn * Kn; idx += 256) {
        int i = idx >> 6, k = idx & 63;
        float s = 0.f;
        for (int j = 0; j <= k; j++) s += sD[i * 64 + j] * sL[k * 65 + j];
        gW[n * Fn * Kn + idx] = s;
    }
}

// ============================================================================
// Kernel 2: main fused GEMM. grid = (B/128, N). Per CTA: tile of 128 samples,
// one cluster n. z[b][k] = sum_i x[b][i] W[n][i][k]; q[b] = sum_k z^2.
// x tile stored transposed in smem so row-pairs load as b64 for f32x2 FMA.
// ============================================================================
#define XPITCH 130   // floats per column of sXT (even -> 8B-aligned pairs, few conflicts)

__global__ void __launch_bounds__(256, 2) main_kernel(const float* __restrict__ x) {
    extern __shared__ float sm[];
    float* sXT = sm;                    // [F=128][XPITCH] transposed x tile
    float* sW  = sm + Fn * XPITCH;      // [F=128][K=64]

    const int bt = blockIdx.x, n = blockIdx.y, tid = threadIdx.x;

    // Load + transpose x tile (128 rows x 128 cols)
    const float4* gx4 = (const float4*)(x + (size_t)bt * 128 * Fn);
    #pragma unroll
    for (int k = 0; k < 16; k++) {
        int v = tid + k * 256;          // float4 index 0..4095
        int row = v >> 5;               // 32 float4 per row
        int c4  = v & 31;
        float4 f = gx4[v];
        sXT[(c4 * 4 + 0) * XPITCH + row] = f.x;
        sXT[(c4 * 4 + 1) * XPITCH + row] = f.y;
        sXT[(c4 * 4 + 2) * XPITCH + row] = f.z;
        sXT[(c4 * 4 + 3) * XPITCH + row] = f.w;
    }
    // Load W[n]
    const float* gw = gW + n * Fn * Kn;
    for (int idx = tid; idx < Fn * Kn; idx += 256) sW[idx] = gw[idx];
    __syncthreads();

    // 8 rows x 4 cols microtile per thread, rows as 4 packed pairs
    const int ty = tid >> 4, tx = tid & 15;
    const int r0 = ty * 8, c0 = tx * 4;

    unsigned long long acc[4][4];
    #pragma unroll
    for (int p = 0; p < 4; p++)
        #pragma unroll
        for (int c = 0; c < 4; c++) acc[p][c] = 0ull;

    #pragma unroll 4
    for (int i = 0; i < Fn; i++) {
        float4 w4 = *(const float4*)&sW[i * 64 + c0];
        unsigned long long wd[4];
        wd[0] = pack2(w4.x, w4.x);
        wd[1] = pack2(w4.y, w4.y);
        wd[2] = pack2(w4.z, w4.z);
        wd[3] = pack2(w4.w, w4.w);
        unsigned long long xp[4];
        #pragma unroll
        for (int p = 0; p < 4; p++)
            xp[p] = *(const unsigned long long*)&sXT[i * XPITCH + r0 + 2 * p];
        #pragma unroll
        for (int p = 0; p < 4; p++)
            #pragma unroll
            for (int c = 0; c < 4; c++)
                fma2(acc[p][c], xp[p], wd[c]);
    }

    // Square-reduce over this thread's 4 k-columns -> 8 row partials
    float rs[8];
    #pragma unroll
    for (int j = 0; j < 8; j++) rs[j] = 0.f;
    #pragma unroll
    for (int p = 0; p < 4; p++) {
        #pragma unroll
        for (int c = 0; c < 4; c++) {
            float lo, hi;
            unpack2(acc[p][c], lo, hi);
            rs[2 * p]     += lo * lo;
            rs[2 * p + 1] += hi * hi;
        }
    }

    __syncthreads();                    // done reading sW; reuse as reduction buffer
    float* sP = sW;                     // [128 rows][16 tx]
    #pragma unroll
    for (int j = 0; j < 8; j++) sP[(r0 + j) * 16 + tx] = rs[j];
    __syncthreads();

    if (tid < 128) {
        float q = 0.f;
        #pragma unroll
        for (int t = 0; t < 16; t++) q += sP[tid * 16 + t];
        gQ[n * Bn + bt * 128 + tid] = q;
    }
}

// ============================================================================
// Kernel 3: per-sample argmax over n, ||x||^2, labels + loss reduction.
// ============================================================================
__global__ void __launch_bounds__(256) reduce_kernel(const float* __restrict__ x,
                                                     float* __restrict__ out,
                                                     int out_size) {
    __shared__ float sred[256];
    const int b = blockIdx.x * 256 + threadIdx.x;

    float best = -1e30f;
    int bi = 0;
    #pragma unroll 4
    for (int n = 0; n < Nn; n++) {
        float v = gQ[n * Bn + b];
        if (v > best) { best = v; bi = n; }   // strict > == first-index tie-break
    }

    float xn2 = 0.f;
    const float4* xb = (const float4*)(x + (size_t)b * Fn);
    #pragma unroll
    for (int i = 0; i < Fn / 4; i++) {
        float4 f = xb[i];
        xn2 += f.x * f.x + f.y * f.y + f.z * f.z + f.w * f.w;
    }
    float resid = xn2 - best;   // == ||x - x_hat(label)||^2

    if (out_size >= Bn + 1) {
        out[1 + b] = (float)bi;
    } else if (out_size == Bn) {
        out[b] = (float)bi;
    }

    sred[threadIdx.x] = resid;
    __syncthreads();
    for (int s = 128; s > 0; s >>= 1) {
        if (threadIdx.x < s) sred[threadIdx.x] += sred[threadIdx.x + s];
        __syncthreads();
    }
    if (threadIdx.x == 0 && out_size != Bn) atomicAdd(&out[0], sred[0]);
}

// ============================================================================
extern "C" void kernel_launch(void* const* d_in, const int* in_sizes, int n_in,
                              void* d_out, int out_size) {
    // Disambiguate inputs by element count (x: 16384*128, D: 64*128*64)
    const float* x;
    const float* D;
    if (in_sizes[0] == Bn * Fn) { x = (const float*)d_in[0]; D = (const float*)d_in[1]; }
    else                        { x = (const float*)d_in[1]; D = (const float*)d_in[0]; }
    float* out = (float*)d_out;

    const int SMEM_PREP = (Fn * Kn + 64 * 65 + 64 * 65) * 4;        // 66048 B
    const int SMEM_MAIN = (Fn * XPITCH + Fn * Kn) * 4;              // 99328 B
    cudaFuncSetAttribute(prep_kernel, cudaFuncAttributeMaxDynamicSharedMemorySize, SMEM_PREP);
    cudaFuncSetAttribute(main_kernel, cudaFuncAttributeMaxDynamicSharedMemorySize, SMEM_MAIN);

    prep_kernel<<<Nn, 256, SMEM_PREP>>>(D);
    main_kernel<<<dim3(Bn / 128, Nn), 256, SMEM_MAIN>>>(x);
    if (out_size != Bn) cudaMemsetAsync(d_out, 0, sizeof(float));   // zero loss slot
    reduce_kernel<<<Bn / 256, 256>>>(x, out, out_size);
}

// round 7
// speedup vs baseline: 1.9161x; 1.9161x over previous
#include <cuda_runtime.h>
#include <cuda_bf16.h>
#include <math.h>
#include <stdint.h>

// Problem dims
#define Bn 16384
#define Nn 64
#define Fn 128
#define Kn 64
#define NG 8          // clusters per CTA in main kernel
#define THRV 1e-3f    // ambiguity threshold (relative)

// ---------------- device scratch (no allocations allowed) ----------------
__device__ __align__(16) __nv_bfloat16 gXhi[Bn * Fn];        // 4 MB
__device__ __align__(16) __nv_bfloat16 gXlo[Bn * Fn];        // 4 MB
__device__ __align__(16) __nv_bfloat16 gWtHi[Nn * Kn * Fn];  // 1 MB  [n][k][i]
__device__ __align__(16) __nv_bfloat16 gWtLo[Nn * Kn * Fn];  // 1 MB
__device__ float gWf[Nn * Fn * Kn];                          // 2 MB  [n][i][k] fp32 (refine)
__device__ float gQ[Nn * Bn];                                // 4 MB
__device__ int   gFlagCnt;
__device__ int   gFlagIdx[Bn];
__device__ float gFlagQ[Bn];

// ---------------- PTX helpers (portable sm_80+ subset) ----------------
__device__ __forceinline__ uint32_t smem_u32(const void* p) {
    uint32_t a;
    asm("{ .reg .u64 t; cvta.to.shared.u64 t, %1; cvt.u32.u64 %0, t; }" : "=r"(a) : "l"(p));
    return a;
}
__device__ __forceinline__ void ldm_x4(uint32_t& r0, uint32_t& r1, uint32_t& r2, uint32_t& r3,
                                       uint32_t addr) {
    asm volatile("ldmatrix.sync.aligned.m8n8.x4.shared.b16 {%0,%1,%2,%3}, [%4];"
                 : "=r"(r0), "=r"(r1), "=r"(r2), "=r"(r3) : "r"(addr));
}
__device__ __forceinline__ void mma_bf16(float* c, const uint32_t* a, const uint32_t* b) {
    asm volatile(
        "mma.sync.aligned.m16n8k16.row.col.f32.bf16.bf16.f32 "
        "{%0,%1,%2,%3}, {%4,%5,%6,%7}, {%8,%9}, {%0,%1,%2,%3};"
        : "+f"(c[0]), "+f"(c[1]), "+f"(c[2]), "+f"(c[3])
        : "r"(a[0]), "r"(a[1]), "r"(a[2]), "r"(a[3]), "r"(b[0]), "r"(b[1]));
}
#define CP_ASYNC16(dst, src) asm volatile("cp.async.cg.shared.global [%0], [%1], 16;" :: "r"(dst), "l"(src))
#define CP_COMMIT()          asm volatile("cp.async.commit_group;")
#define CP_WAIT0()           asm volatile("cp.async.wait_group 0;" ::: "memory")

// swizzled smem offset for a 16B chunk (row stride 256B = 128 bf16, 16 chunks/row)
__device__ __forceinline__ uint32_t swz(int r, int c) {
    return (uint32_t)(r * 256 + ((c ^ (r & 7)) << 4));
}

// ============================================================================
// Kernel 0: split x into bf16 hi/lo; zero flag counter
// ============================================================================
__global__ void __launch_bounds__(256) convert_x_kernel(const float* __restrict__ x) {
    if (blockIdx.x == 0 && threadIdx.x == 0) gFlagCnt = 0;
    int base = (blockIdx.x * 256 + threadIdx.x) * 8;
    float4 a = *(const float4*)(x + base);
    float4 b = *(const float4*)(x + base + 4);
    float v[8] = {a.x, a.y, a.z, a.w, b.x, b.y, b.z, b.w};
    #pragma unroll
    for (int i = 0; i < 8; i++) {
        __nv_bfloat16 hi = __float2bfloat16_rn(v[i]);
        __nv_bfloat16 lo = __float2bfloat16_rn(v[i] - __bfloat162float(hi));
        gXhi[base + i] = hi;
        gXlo[base + i] = lo;
    }
}

// ============================================================================
// Kernel 1 (prep): per cluster n: A = D^T D ; div-free Cholesky ; solve
// W L^T = D per feature row ; emit Wt (bf16 hi/lo, [n][k][i]) and fp32 W ([n][i][k]).
// ============================================================================
__global__ void __launch_bounds__(256) prep_kernel(const float* __restrict__ D) {
    extern __shared__ float sm[];
    float* sD   = sm;                         // [128][64]
    float* sA   = sD + Fn * Kn;               // [64][65]
    float* sInv = sA + 64 * 65;               // [64]
    float* sW   = sInv + 64;                  // [128][65]

    const int n = blockIdx.x, tid = threadIdx.x;
    const float* Dn = D + n * Fn * Kn;

    for (int idx = tid; idx < Fn * Kn; idx += 256) sD[idx] = Dn[idx];
    __syncthreads();

    {   // DTD, 4x4 microtile per thread
        const int j0 = (tid >> 4) * 4, k0 = (tid & 15) * 4;
        float acc[4][4];
        #pragma unroll
        for (int a = 0; a < 4; a++)
            #pragma unroll
            for (int b = 0; b < 4; b++) acc[a][b] = 0.f;
        for (int i = 0; i < Fn; i++) {
            float av[4], bv[4];
            #pragma unroll
            for (int a = 0; a < 4; a++) av[a] = sD[i * 64 + j0 + a];
            #pragma unroll
            for (int b = 0; b < 4; b++) bv[b] = sD[i * 64 + k0 + b];
            #pragma unroll
            for (int a = 0; a < 4; a++)
                #pragma unroll
                for (int b = 0; b < 4; b++) acc[a][b] += av[a] * bv[b];
        }
        #pragma unroll
        for (int a = 0; a < 4; a++)
            #pragma unroll
            for (int b = 0; b < 4; b++) sA[(j0 + a) * 65 + (k0 + b)] = acc[a][b];
    }
    __syncthreads();

    // Cholesky, divide-free
    for (int k = 0; k < 64; k++) {
        if (tid == 0) {
            float a = sA[k * 65 + k];
            float r = rsqrtf(a);
            sA[k * 65 + k] = a * r;
            sInv[k] = r;
        }
        __syncthreads();
        if (tid > k && tid < 64) sA[tid * 65 + k] *= sInv[k];
        __syncthreads();
        for (int idx = tid; idx < 64 * 64; idx += 256) {
            int i = idx >> 6, j = idx & 63;
            if (i > k && j > k && j <= i)
                sA[i * 65 + j] -= sA[i * 65 + k] * sA[j * 65 + k];
        }
        __syncthreads();
    }

    // Solve w L^T = d per feature row i
    if (tid < Fn) {
        const int i = tid;
        float* w = sW + i * 65;
        for (int j = 0; j < 64; j++) {
            float s = sD[i * 64 + j];
            #pragma unroll 4
            for (int m = 0; m < j; m++) s -= sA[j * 65 + m] * w[m];
            w[j] = s * sInv[j];
        }
        for (int k = 0; k < 64; k++) {
            float v = w[k];
            __nv_bfloat16 hi = __float2bfloat16_rn(v);
            __nv_bfloat16 lo = __float2bfloat16_rn(v - __bfloat162float(hi));
            int o = (n * 64 + k) * Fn + i;
            gWtHi[o] = hi;
            gWtLo[o] = lo;
            gWf[((size_t)n * Fn + i) * Kn + k] = v;   // fp32 for refine
        }
    }
}

// ============================================================================
// Kernel 2 (main): mma.sync bf16 3-split GEMM + square-reduce.
// grid (128, 8) x 128 threads. CTA: b-tile of 128 samples x 8 clusters.
// ============================================================================
#define SXH 0
#define SXL 32768
#define SWH 65536
#define SWL 81920
#define SM_TOTAL 98304

__global__ void __launch_bounds__(128) main_kernel() {
    extern __shared__ char smem[];
    const uint32_t sb = smem_u32(smem);
    const int tid = threadIdx.x, wid = tid >> 5, lane = tid & 31;
    const int bt = blockIdx.x;

    // ---- load x tile hi/lo (swizzled, cp.async) ----
    {
        const char* srcH = (const char*)(gXhi + (size_t)bt * 128 * Fn);
        const char* srcL = (const char*)(gXlo + (size_t)bt * 128 * Fn);
        #pragma unroll
        for (int t = 0; t < 16; t++) {
            int id = tid + t * 128;
            int r = id >> 4, c = id & 15;
            uint32_t d = swz(r, c);
            CP_ASYNC16(sb + SXH + d, srcH + r * 256 + c * 16);
            CP_ASYNC16(sb + SXL + d, srcL + r * 256 + c * 16);
        }
    }
    // ---- load W for first cluster ----
    {
        int n0 = blockIdx.y * NG;
        const char* srcH = (const char*)(gWtHi + (size_t)n0 * Kn * Fn);
        const char* srcL = (const char*)(gWtLo + (size_t)n0 * Kn * Fn);
        #pragma unroll
        for (int t = 0; t < 8; t++) {
            int id = tid + t * 128;
            int r = id >> 4, c = id & 15;
            uint32_t d = swz(r, c);
            CP_ASYNC16(sb + SWH + d, srcH + r * 256 + c * 16);
            CP_ASYNC16(sb + SWL + d, srcL + r * 256 + c * 16);
        }
    }
    CP_COMMIT();
    CP_WAIT0();
    __syncthreads();

    const int m0 = wid * 32;

    for (int j = 0; j < NG; j++) {
        const int n = blockIdx.y * NG + j;

        float acc[2][8][4];
        #pragma unroll
        for (int mt = 0; mt < 2; mt++)
            #pragma unroll
            for (int nt = 0; nt < 8; nt++)
                #pragma unroll
                for (int e = 0; e < 4; e++) acc[mt][nt][e] = 0.f;

        #pragma unroll
        for (int ks = 0; ks < 8; ks++) {
            const int c0 = 2 * ks;
            uint32_t Ah[2][4], Al[2][4], Bh[8][2], Bl[8][2];
            #pragma unroll
            for (int mt = 0; mt < 2; mt++) {
                int row = m0 + mt * 16 + (lane & 15);
                int cc  = c0 + (lane >> 4);
                uint32_t d = swz(row, cc);
                ldm_x4(Ah[mt][0], Ah[mt][1], Ah[mt][2], Ah[mt][3], sb + SXH + d);
                ldm_x4(Al[mt][0], Al[mt][1], Al[mt][2], Al[mt][3], sb + SXL + d);
            }
            #pragma unroll
            for (int np = 0; np < 4; np++) {
                int nrow = np * 16 + (lane & 7) + ((lane >> 4) << 3);
                int cc   = c0 + ((lane >> 3) & 1);
                uint32_t d = swz(nrow, cc);
                ldm_x4(Bh[np*2][0], Bh[np*2][1], Bh[np*2+1][0], Bh[np*2+1][1], sb + SWH + d);
                ldm_x4(Bl[np*2][0], Bl[np*2][1], Bl[np*2+1][0], Bl[np*2+1][1], sb + SWL + d);
            }
            #pragma unroll
            for (int mt = 0; mt < 2; mt++)
                #pragma unroll
                for (int nt = 0; nt < 8; nt++) {
                    mma_bf16(acc[mt][nt], Ah[mt], Bh[nt]);   // hi*hi
                    mma_bf16(acc[mt][nt], Ah[mt], Bl[nt]);   // hi*lo
                    mma_bf16(acc[mt][nt], Al[mt], Bh[nt]);   // lo*hi
                }
        }

        // ---- epilogue: q[m] = sum_k z^2 ----
        float pa = 0.f, pb = 0.f, pc = 0.f, pd = 0.f;   // rows lane/4 + {0,8,16,24}
        #pragma unroll
        for (int nt = 0; nt < 8; nt++) {
            pa += acc[0][nt][0] * acc[0][nt][0] + acc[0][nt][1] * acc[0][nt][1];
            pb += acc[0][nt][2] * acc[0][nt][2] + acc[0][nt][3] * acc[0][nt][3];
            pc += acc[1][nt][0] * acc[1][nt][0] + acc[1][nt][1] * acc[1][nt][1];
            pd += acc[1][nt][2] * acc[1][nt][2] + acc[1][nt][3] * acc[1][nt][3];
        }
        #pragma unroll
        for (int o = 1; o <= 2; o <<= 1) {
            pa += __shfl_xor_sync(0xFFFFFFFFu, pa, o);
            pb += __shfl_xor_sync(0xFFFFFFFFu, pb, o);
            pc += __shfl_xor_sync(0xFFFFFFFFu, pc, o);
            pd += __shfl_xor_sync(0xFFFFFFFFu, pd, o);
        }
        if ((lane & 3) == 0) {
            int r = lane >> 2;
            float* q = gQ + (size_t)n * Bn + bt * 128 + m0;
            q[r]      = pa;
            q[r + 8]  = pb;
            q[r + 16] = pc;
            q[r + 24] = pd;
        }

        // ---- load next cluster's W ----
        if (j + 1 < NG) {
            __syncthreads();
            int nn = blockIdx.y * NG + j + 1;
            const char* srcH = (const char*)(gWtHi + (size_t)nn * Kn * Fn);
            const char* srcL = (const char*)(gWtLo + (size_t)nn * Kn * Fn);
            #pragma unroll
            for (int t = 0; t < 8; t++) {
                int id = tid + t * 128;
                int r = id >> 4, c = id & 15;
                uint32_t d = swz(r, c);
                CP_ASYNC16(sb + SWH + d, srcH + r * 256 + c * 16);
                CP_ASYNC16(sb + SWL + d, srcL + r * 256 + c * 16);
            }
            CP_COMMIT();
            CP_WAIT0();
            __syncthreads();
        }
    }
}

// ============================================================================
// Kernel 3 (A): per-sample argmax, flag ambiguous, labels + loss.
// ============================================================================
__global__ void __launch_bounds__(256) reduce_kernel(const float* __restrict__ x,
                                                     float* __restrict__ out,
                                                     int out_size) {
    __shared__ float sred[256];
    const int b = blockIdx.x * 256 + threadIdx.x;

    float q1 = -1e30f, q2 = -1e30f;
    int i1 = 0;
    #pragma unroll 4
    for (int n = 0; n < Nn; n++) {
        float v = gQ[n * Bn + b];
        if (v > q1)      { q2 = q1; q1 = v; i1 = n; }
        else if (v > q2) { q2 = v; }
    }

    float xn2 = 0.f;
    const float4* xb = (const float4*)(x + (size_t)b * Fn);
    #pragma unroll
    for (int i = 0; i < Fn / 4; i++) {
        float4 f = xb[i];
        xn2 += f.x * f.x + f.y * f.y + f.z * f.z + f.w * f.w;
    }
    float resid = xn2 - q1;

    if (out_size >= Bn + 1)  out[1 + b] = (float)i1;
    else if (out_size == Bn) out[b] = (float)i1;

    if (q1 - q2 < q1 * THRV) {   // ambiguous: refine later
        int slot = atomicAdd(&gFlagCnt, 1);
        gFlagIdx[slot] = b;
        gFlagQ[slot] = q1;
    }

    sred[threadIdx.x] = resid;
    __syncthreads();
    for (int s = 128; s > 0; s >>= 1) {
        if (threadIdx.x < s) sred[threadIdx.x] += sred[threadIdx.x + s];
        __syncthreads();
    }
    if (threadIdx.x == 0 && out_size != Bn) atomicAdd(&out[0], sred[0]);
}

// ============================================================================
// Kernel 4 (B): exact fp32 refinement of ambiguous samples.
// One warp per flagged sample; candidates = clusters within THR of approx max.
// ============================================================================
__global__ void __launch_bounds__(128) refine_kernel(const float* __restrict__ x,
                                                     float* __restrict__ out,
                                                     int out_size) {
    __shared__ float sx[4][Fn];
    const int wid = threadIdx.x >> 5, lane = threadIdx.x & 31;
    const int wglobal = blockIdx.x * 4 + wid;
    const int cnt = gFlagCnt;

    for (int fi = wglobal; fi < cnt; fi += gridDim.x * 4) {
        const int b = gFlagIdx[fi];
        const float qA = gFlagQ[fi];

        // load x[b] into this warp's smem slice
        #pragma unroll
        for (int t = 0; t < 4; t++) sx[wid][lane + t * 32] = x[(size_t)b * Fn + lane + t * 32];
        __syncwarp();

        const float cut = qA - qA * THRV;
        float bestq = -1e30f;
        int bestn = 0;
        for (int n = 0; n < Nn; n++) {
            float qn = gQ[n * Bn + b];    // broadcast read
            if (qn < cut) continue;
            // exact fp32 q for (b, n): lanes own k = 2*lane, 2*lane+1
            const float* Wn = gWf + (size_t)n * Fn * Kn + 2 * lane;
            float z0 = 0.f, z1 = 0.f;
            #pragma unroll 4
            for (int i = 0; i < Fn; i++) {
                float xi = sx[wid][i];
                float2 wv = *(const float2*)(Wn + i * Kn);
                z0 += xi * wv.x;
                z1 += xi * wv.y;
            }
            float qp = z0 * z0 + z1 * z1;
            #pragma unroll
            for (int o = 16; o; o >>= 1) qp += __shfl_xor_sync(0xFFFFFFFFu, qp, o);
            if (qp > bestq) { bestq = qp; bestn = n; }   // ascending n: first wins ties
        }
        if (lane == 0) {
            if (out_size >= Bn + 1)  out[1 + b] = (float)bestn;
            else if (out_size == Bn) out[b] = (float)bestn;
            if (out_size != Bn) atomicAdd(&out[0], qA - bestq);  // fix loss term
        }
        __syncwarp();
    }
}

// ============================================================================
extern "C" void kernel_launch(void* const* d_in, const int* in_sizes, int n_in,
                              void* d_out, int out_size) {
    const float* x;
    const float* D;
    if (in_sizes[0] == Bn * Fn) { x = (const float*)d_in[0]; D = (const float*)d_in[1]; }
    else                        { x = (const float*)d_in[1]; D = (const float*)d_in[0]; }
    float* out = (float*)d_out;

    const int SMEM_PREP = (Fn * Kn + 64 * 65 + 64 + Fn * 65) * 4;
    cudaFuncSetAttribute(prep_kernel, cudaFuncAttributeMaxDynamicSharedMemorySize, SMEM_PREP);
    cudaFuncSetAttribute(main_kernel, cudaFuncAttributeMaxDynamicSharedMemorySize, SM_TOTAL);

    convert_x_kernel<<<Bn * Fn / (256 * 8), 256>>>(x);
    prep_kernel<<<Nn, 256, SMEM_PREP>>>(D);
    main_kernel<<<dim3(128, 8), 128, SM_TOTAL>>>();
    if (out_size != Bn) cudaMemsetAsync(d_out, 0, sizeof(float));
    reduce_kernel<<<Bn / 256, 256>>>(x, out, out_size);
    refine_kernel<<<64, 128>>>(x, out, out_size);
}